// round 3
// baseline (speedup 1.0000x reference)
#include <cuda_runtime.h>
#include <cuda_bf16.h>
#include <cstdint>

// ---------------- problem constants ----------------
#define BB 64
#define SS 4096
#define FFEAT 128
#define RANK 16
#define DF 10
#define NCOL 160          // RANK*DF
#define KU 129            // F+1 (ones-concat first)
#define TM 128            // tokens per CTA
#define NTHREADS 512
#define XSTRIDE 280       // bf16 elems per Xs row (cols: [0..128]=hi, [136..264]=lo, rest 0)
#define BSTRIDE 296       // bf16 elems per Bs row  (k:  [0..128]=ah, [144..272]=al, rest 0)

// smem byte offsets (phase-overlaid)
#define XS_OFF   0
#define BS_OFF   71680                 // 128*280*2
#define SMEM_BYTES 166400              // BS_OFF + 160*296*2
#define G_OFF    0                     // fp32 [128][164]  (83968 B)
#define GSTR     164
#define SEQ_OFF  83968                 // fp32 [128][12]
#define W1_OFF   90112                 // fp32 [10][128]
#define B1_OFF   95232                 // fp32 [128]
#define W2_OFF   95744                 // fp32 [128][2]
#define H_OFF    96768                 // fp32 [128][136] -> ends exactly at 166400
#define HSTR     136

// split factor matrices, N-major for ldmatrix B-operand: [mod][n=r*10+d][k]
__device__ __nv_bfloat16 g_A3[2][NCOL][BSTRIDE];

// ---------------- prep: bf16 hi/lo split of factors, fold fusion_weights into imu ----------------
__global__ void prep_kernel(const float* __restrict__ imu_factor,
                            const float* __restrict__ vid_factor,
                            const float* __restrict__ fusion_w)
{
    int idx = blockIdx.x * blockDim.x + threadIdx.x;
    const int total = 2 * NCOL * BSTRIDE;
    if (idx >= total) return;
    int mod = idx / (NCOL * BSTRIDE);
    int n   = (idx / BSTRIDE) % NCOL;
    int k   = idx % BSTRIDE;
    int r = n / DF, d = n % DF;
    const float* fac = (mod == 0) ? imu_factor : vid_factor;
    float scale = (mod == 0) ? fusion_w[r] : 1.0f;

    __nv_bfloat16 outv = __float2bfloat16(0.0f);
    if (k < KU) {
        float v = scale * fac[(r * KU + k) * DF + d];
        outv = __float2bfloat16(v);                       // ah
    } else if (k >= 144 && k < 144 + KU) {
        int f = k - 144;
        float v = scale * fac[(r * KU + f) * DF + d];
        __nv_bfloat16 h = __float2bfloat16(v);
        outv = __float2bfloat16(v - __bfloat162float(h)); // al
    }
    g_A3[mod][n][k] = outv;
}

// ---------------- mma helpers ----------------
__device__ __forceinline__ uint32_t smem_u32(const void* p) {
    return (uint32_t)__cvta_generic_to_shared(p);
}
__device__ __forceinline__ void ldsm_x4(uint32_t r[4], uint32_t addr) {
    asm volatile("ldmatrix.sync.aligned.m8n8.x4.shared.b16 {%0,%1,%2,%3}, [%4];"
                 : "=r"(r[0]), "=r"(r[1]), "=r"(r[2]), "=r"(r[3]) : "r"(addr));
}
__device__ __forceinline__ void ldsm_x2(uint32_t r[2], uint32_t addr) {
    asm volatile("ldmatrix.sync.aligned.m8n8.x2.shared.b16 {%0,%1}, [%2];"
                 : "=r"(r[0]), "=r"(r[1]) : "r"(addr));
}
__device__ __forceinline__ void mma_bf16(float d[4], const uint32_t a[4], const uint32_t b[2]) {
    asm volatile("mma.sync.aligned.m16n8k16.row.col.f32.bf16.bf16.f32 "
                 "{%0,%1,%2,%3}, {%4,%5,%6,%7}, {%8,%9}, {%0,%1,%2,%3};"
                 : "+f"(d[0]), "+f"(d[1]), "+f"(d[2]), "+f"(d[3])
                 : "r"(a[0]), "r"(a[1]), "r"(a[2]), "r"(a[3]), "r"(b[0]), "r"(b[1]));
}

// ---------------- main fused kernel ----------------
__global__ void __launch_bounds__(NTHREADS, 1)
fusion_main(const float* __restrict__ imu_h,
            const float* __restrict__ vid_h,
            const float* __restrict__ anthro,
            const float* __restrict__ fusion_bias,
            const float* __restrict__ W1,
            const float* __restrict__ b1,
            const float* __restrict__ W2,
            const float* __restrict__ b2,
            float* __restrict__ out)
{
    extern __shared__ char smem[];
    __nv_bfloat16* Xs = (__nv_bfloat16*)(smem + XS_OFF);
    __nv_bfloat16* Bs = (__nv_bfloat16*)(smem + BS_OFF);
    float* G    = (float*)(smem + G_OFF);
    float* seqs = (float*)(smem + SEQ_OFF);
    float* W1s  = (float*)(smem + W1_OFF);
    float* b1s  = (float*)(smem + B1_OFF);
    float* W2s  = (float*)(smem + W2_OFF);
    float* hs   = (float*)(smem + H_OFF);

    const int tid  = threadIdx.x;
    const int warp = tid >> 5, lane = tid & 31;
    const int wm = warp & 3;    // 4 M groups of 32 rows
    const int wn = warp >> 2;   // 4 N groups of 40 cols
    const long tokenBase = (long)blockIdx.x * TM;

    // zero Xs (pads stay zero across phases), then the ones column
    for (int i = tid; i < TM * XSTRIDE / 2; i += NTHREADS)
        ((uint32_t*)Xs)[i] = 0u;
    __syncthreads();
    if (tid < TM) Xs[tid * XSTRIDE + 0] = __float2bfloat16(1.0f);

    float acc0[2][5][4];  // imu  Z
    float acc1[2][5][4];  // vid  Z
    #pragma unroll
    for (int a = 0; a < 2; ++a)
        #pragma unroll
        for (int b_ = 0; b_ < 5; ++b_)
            #pragma unroll
            for (int c = 0; c < 4; ++c) { acc0[a][b_][c] = 0.f; acc1[a][b_][c] = 0.f; }

    auto run_modality = [&](int mod, const float* __restrict__ src, float (&acc)[2][5][4]) {
        __syncthreads();  // previous phase readers done before restage
        // stage X tile: fp32 -> (hi | lo) bf16, ones column already set
        const float4* src4 = (const float4*)(src + tokenBase * FFEAT);
        for (int i = tid; i < TM * FFEAT / 4; i += NTHREADS) {
            int t = i >> 5;          // 32 float4 per token row
            int f = (i & 31) * 4;
            float4 v = src4[i];
            float vals[4] = {v.x, v.y, v.z, v.w};
            #pragma unroll
            for (int c = 0; c < 4; ++c) {
                __nv_bfloat16 h = __float2bfloat16(vals[c]);
                __nv_bfloat16 l = __float2bfloat16(vals[c] - __bfloat162float(h));
                Xs[t * XSTRIDE + 1 + f + c]   = h;
                Xs[t * XSTRIDE + 137 + f + c] = l;
            }
        }
        // stage factor tile (L2-resident across CTAs)
        const uint4* bsrc = (const uint4*)&g_A3[mod][0][0];
        for (int i = tid; i < (NCOL * BSTRIDE * 2 / 16); i += NTHREADS)
            ((uint4*)Bs)[i] = bsrc[i];
        __syncthreads();

        // three split passes: xh*ah, xl*ah, xh*al
        const int xoffs[3] = {0, 136, 0};
        const int aoffs[3] = {0, 0, 144};
        #pragma unroll
        for (int pass = 0; pass < 3; ++pass) {
            const int xo = xoffs[pass], ao = aoffs[pass];
            for (int ks = 0; ks < 9; ++ks) {
                const int k0 = ks * 16;
                uint32_t afrag[2][4], bfrag[5][2];
                #pragma unroll
                for (int mi = 0; mi < 2; ++mi) {
                    int row = wm * 32 + mi * 16 + (lane & 15);
                    int col = xo + k0 + (lane >> 4) * 8;
                    ldsm_x4(afrag[mi], smem_u32(&Xs[row * XSTRIDE + col]));
                }
                #pragma unroll
                for (int ni = 0; ni < 5; ++ni) {
                    int l = lane & 15;
                    int nrow = wn * 40 + ni * 8 + (l & 7);
                    int col  = ao + k0 + (l >> 3) * 8;
                    ldsm_x2(bfrag[ni], smem_u32(&Bs[nrow * BSTRIDE + col]));
                }
                #pragma unroll
                for (int mi = 0; mi < 2; ++mi)
                    #pragma unroll
                    for (int ni = 0; ni < 5; ++ni)
                        mma_bf16(acc[mi][ni], afrag[mi], bfrag[ni]);
            }
        }
    };

    run_modality(0, imu_h, acc0);
    run_modality(1, vid_h, acc1);
    __syncthreads();  // mma done everywhere; Xs/Bs now dead -> overlay G etc.

    // rank-wise products to G[t][c] (c = r*10+d; fusion_weights already folded into imu factors)
    #pragma unroll
    for (int mi = 0; mi < 2; ++mi)
        #pragma unroll
        for (int ni = 0; ni < 5; ++ni) {
            int row0 = wm * 32 + mi * 16 + (lane >> 2);
            int col0 = wn * 40 + ni * 8 + 2 * (lane & 3);
            G[row0 * GSTR + col0]       = acc0[mi][ni][0] * acc1[mi][ni][0];
            G[row0 * GSTR + col0 + 1]   = acc0[mi][ni][1] * acc1[mi][ni][1];
            G[(row0+8) * GSTR + col0]   = acc0[mi][ni][2] * acc1[mi][ni][2];
            G[(row0+8) * GSTR + col0+1] = acc0[mi][ni][3] * acc1[mi][ni][3];
        }
    // stage MLP weights (disjoint smem regions)
    for (int i = tid; i < DF * FFEAT; i += NTHREADS) W1s[i] = W1[i];
    if (tid < FFEAT)     b1s[tid] = b1[tid];
    if (tid < FFEAT * 2) W2s[tid] = W2[tid];
    __syncthreads();

    // seq[t][d] = bias[d] + sum_r G[t][r*10+d]
    for (int i = tid; i < TM * DF; i += NTHREADS) {
        int t = i / DF, d = i % DF;
        float s = fusion_bias[d];
        #pragma unroll
        for (int r = 0; r < RANK; ++r) s += G[t * GSTR + r * DF + d];
        seqs[t * 12 + d] = s;
    }
    __syncthreads();

    // h = relu(seq @ W1 + b1)
    for (int i = tid; i < TM * FFEAT; i += NTHREADS) {
        int t = i >> 7, j = i & 127;
        float s = b1s[j];
        #pragma unroll
        for (int d = 0; d < DF; ++d) s += seqs[t * 12 + d] * W1s[d * FFEAT + j];
        hs[t * HSTR + j] = fmaxf(s, 0.f);
    }
    __syncthreads();

    // out = (h @ W2 + b2) / (anthro0*anthro1)
    if (tid < TM * 2) {
        int t = tid >> 1, o = tid & 1;
        float s = b2[o];
        #pragma unroll 8
        for (int j = 0; j < FFEAT; ++j) s += hs[t * HSTR + j] * W2s[j * 2 + o];
        long token = tokenBase + t;
        int bi = (int)(token >> 12);   // S = 4096
        float inv = 1.0f / (anthro[bi * 2] * anthro[bi * 2 + 1]);
        out[token * 2 + o] = s * inv;
    }
}

// ---------------- launch ----------------
extern "C" void kernel_launch(void* const* d_in, const int* in_sizes, int n_in,
                              void* d_out, int out_size)
{
    (void)in_sizes; (void)n_in; (void)out_size;
    const float* imu_h       = (const float*)d_in[0];
    const float* vid_h       = (const float*)d_in[1];
    const float* anthro      = (const float*)d_in[2];
    const float* imu_factor  = (const float*)d_in[3];
    const float* vid_factor  = (const float*)d_in[4];
    const float* fusion_w    = (const float*)d_in[5];
    const float* fusion_b    = (const float*)d_in[6];
    const float* W1          = (const float*)d_in[7];
    const float* b1          = (const float*)d_in[8];
    const float* W2          = (const float*)d_in[9];
    const float* b2          = (const float*)d_in[10];
    float* out = (float*)d_out;

    cudaFuncSetAttribute(fusion_main, cudaFuncAttributeMaxDynamicSharedMemorySize, SMEM_BYTES);

    const int prep_total = 2 * NCOL * BSTRIDE;
    prep_kernel<<<(prep_total + 255) / 256, 256>>>(imu_factor, vid_factor, fusion_w);
    fusion_main<<<(BB * SS) / TM, NTHREADS, SMEM_BYTES>>>(
        imu_h, vid_h, anthro, fusion_b, W1, b1, W2, b2, out);
}

// round 4
// speedup vs baseline: 1.9491x; 1.9491x over previous
#include <cuda_runtime.h>
#include <cuda_bf16.h>
#include <cstdint>

#define NTILES 2048
#define GRID 148
#define TM 128
#define NTHREADS 256
#define RANK 16
#define DF 10
#define NCOL 160
#define XSTRIDE 264        // hi 0..127, ones 128, pad 129..135, lo 136..263
#define BSTRIDE 280        // ah 0..128(bias@128), pad, al 144..271, pad
#define GSTR 164

// smem offsets
#define XS0_OFF 0
#define XS1_OFF 67584
#define BS_OFF  135168      // 89600 B
#define W1S_OFF 224768
#define B1S_OFF 229888
#define ALB_OFF 230400
#define FB_OFF  231680
#define SMEM_BYTES 231720

__device__ __nv_bfloat16 g_A3[2][NCOL][BSTRIDE];
__device__ float g_albias[2 * NCOL];

// ---------- prep ----------
__global__ void prep_kernel(const float* __restrict__ imu_factor,
                            const float* __restrict__ vid_factor,
                            const float* __restrict__ fusion_w)
{
    int idx = blockIdx.x * blockDim.x + threadIdx.x;
    const int total = 2 * NCOL * BSTRIDE;
    if (idx < total) {
        int mod = idx / (NCOL * BSTRIDE);
        int n = (idx / BSTRIDE) % NCOL;
        int k = idx % BSTRIDE;
        int r = n / DF, d = n % DF;
        const float* fac = mod ? vid_factor : imu_factor;
        float scale = mod ? 1.0f : fusion_w[r];
        __nv_bfloat16 o = __float2bfloat16(0.0f);
        if (k <= 128) {
            int kr = (k == 128) ? 0 : k + 1;
            o = __float2bfloat16(scale * fac[(r * 129 + kr) * DF + d]);
        } else if (k >= 144 && k < 272) {
            int kr = k - 143;                       // 1..128
            float v = scale * fac[(r * 129 + kr) * DF + d];
            __nv_bfloat16 h = __float2bfloat16(v);
            o = __float2bfloat16(v - __bfloat162float(h));
        }
        g_A3[mod][n][k] = o;
    } else if (idx < total + 2 * NCOL) {
        int j = idx - total;
        int mod = j / NCOL, n = j % NCOL;
        int r = n / DF, d = n % DF;
        const float* fac = mod ? vid_factor : imu_factor;
        float scale = mod ? 1.0f : fusion_w[r];
        float vb = scale * fac[(r * 129 + 0) * DF + d];
        g_albias[j] = vb - __bfloat162float(__float2bfloat16(vb));
    }
}

// ---------- asm helpers ----------
__device__ __forceinline__ uint32_t smem_u32(const void* p) {
    return (uint32_t)__cvta_generic_to_shared(p);
}
__device__ __forceinline__ void ldsm_x4(uint32_t r[4], uint32_t a) {
    asm volatile("ldmatrix.sync.aligned.m8n8.x4.shared.b16 {%0,%1,%2,%3}, [%4];"
                 : "=r"(r[0]), "=r"(r[1]), "=r"(r[2]), "=r"(r[3]) : "r"(a));
}
__device__ __forceinline__ void ldsm_x2(uint32_t r[2], uint32_t a) {
    asm volatile("ldmatrix.sync.aligned.m8n8.x2.shared.b16 {%0,%1}, [%2];"
                 : "=r"(r[0]), "=r"(r[1]) : "r"(a));
}
__device__ __forceinline__ void mma_bf16(float d[4], const uint32_t a[4], const uint32_t b[2]) {
    asm volatile("mma.sync.aligned.m16n8k16.row.col.f32.bf16.bf16.f32 "
                 "{%0,%1,%2,%3}, {%4,%5,%6,%7}, {%8,%9}, {%0,%1,%2,%3};"
                 : "+f"(d[0]), "+f"(d[1]), "+f"(d[2]), "+f"(d[3])
                 : "r"(a[0]), "r"(a[1]), "r"(a[2]), "r"(a[3]), "r"(b[0]), "r"(b[1]));
}
#define CPA16(sa, gp) asm volatile("cp.async.cg.shared.global [%0], [%1], 16;" :: "r"(sa), "l"(gp))
#define CPCOMMIT() asm volatile("cp.async.commit_group;" ::: "memory")
#define CPWAIT(n)  asm volatile("cp.async.wait_group %0;" :: "n"(n) : "memory")

__device__ __forceinline__ uint32_t pack_bf2(float a, float b) {
    __nv_bfloat162 t = __floats2bfloat162_rn(a, b);
    return *reinterpret_cast<uint32_t*>(&t);
}

// ---------- main ----------
__global__ void __launch_bounds__(NTHREADS, 1)
fusion_main(const float* __restrict__ imu_h,
            const float* __restrict__ vid_h,
            const float* __restrict__ anthro,
            const float* __restrict__ fusion_bias,
            const float* __restrict__ W1,
            const float* __restrict__ b1,
            const float* __restrict__ W2,
            const float* __restrict__ b2,
            float* __restrict__ out)
{
    extern __shared__ char smem[];
    const int tid = threadIdx.x;
    const int warp = tid >> 5, lane = tid & 31;
    const int wm = warp & 1, wn = warp >> 1;

    float* W1S = (float*)(smem + W1S_OFF);
    float* B1S = (float*)(smem + B1S_OFF);
    float* ALB = (float*)(smem + ALB_OFF);
    float* FB  = (float*)(smem + FB_OFF);

    // static constants (once per persistent CTA)
    for (int i = tid; i < 1280; i += NTHREADS) W1S[i] = W1[i];
    if (tid < 128) B1S[tid] = b1[tid];
    for (int i = tid; i < 320; i += NTHREADS) ALB[i] = g_albias[i];
    if (tid < DF) FB[tid] = fusion_bias[tid];

    auto issue_x = [&](int reg_off, const float* src, int tile) {
        uint32_t base = smem_u32(smem + reg_off);
        const char* g = (const char*)(src + (long)tile * TM * 128);
        for (int i = tid; i < 4096; i += NTHREADS) CPA16(base + i * 16, g + i * 16);
        CPCOMMIT();
    };
    auto issue_b = [&](int mod) {
        uint32_t base = smem_u32(smem + BS_OFF);
        const char* g = (const char*)&g_A3[mod][0][0];
        for (int i = tid; i < 5600; i += NTHREADS) CPA16(base + i * 16, g + i * 16);
        CPCOMMIT();
    };
    // in-place fp32[128][128] -> bf16 hi/lo (stride XSTRIDE)
    auto convert_x = [&](int reg_off) {
        char* base = smem + reg_off;
        const int t = tid >> 1, half = tid & 1;
        float4 raw[16];
        const float4* rp = (const float4*)base + t * 32 + half * 16;
        #pragma unroll
        for (int j = 0; j < 16; ++j) raw[j] = rp[j];
        __syncthreads();
        __nv_bfloat16* xr = (__nv_bfloat16*)base + t * XSTRIDE + half * 64;
        #pragma unroll
        for (int j = 0; j < 16; ++j) {
            float4 v = raw[j];
            float h0 = __bfloat162float(__float2bfloat16(v.x));
            float h1 = __bfloat162float(__float2bfloat16(v.y));
            float h2 = __bfloat162float(__float2bfloat16(v.z));
            float h3 = __bfloat162float(__float2bfloat16(v.w));
            uint2 hi = make_uint2(pack_bf2(v.x, v.y), pack_bf2(v.z, v.w));
            uint2 lo = make_uint2(pack_bf2(v.x - h0, v.y - h1), pack_bf2(v.z - h2, v.w - h3));
            *(uint2*)(xr + j * 4) = hi;
            *(uint2*)(xr + 136 + j * 4) = lo;
        }
        if (half == 0) {
            __nv_bfloat16* row = (__nv_bfloat16*)base + t * XSTRIDE;
            row[128] = __float2bfloat16(1.0f);
            #pragma unroll
            for (int c = 129; c < 136; ++c) row[c] = __float2bfloat16(0.0f);
        }
        __syncthreads();
    };

    float acc0[4][5][4], acc1[4][5][4];

    auto mma_all = [&](int reg_off, float (&acc)[4][5][4]) {
        const __nv_bfloat16* Xp = (const __nv_bfloat16*)(smem + reg_off);
        const __nv_bfloat16* Bp = (const __nv_bfloat16*)(smem + BS_OFF);
        #pragma unroll
        for (int pass = 0; pass < 3; ++pass) {
            const int xo = (pass == 1) ? 136 : 0;
            const int ao = (pass == 2) ? 144 : 0;
            const int nks = pass ? 8 : 9;
            for (int ks = 0; ks < nks; ++ks) {
                const int k0 = ks * 16;
                uint32_t af[4][4], bf[5][2];
                #pragma unroll
                for (int mi = 0; mi < 4; ++mi) {
                    int row = wm * 64 + mi * 16 + (lane & 15);
                    ldsm_x4(af[mi], smem_u32(Xp + row * XSTRIDE + xo + k0 + ((lane >> 4) << 3)));
                }
                const int l = lane & 15;
                #pragma unroll
                for (int ni = 0; ni < 5; ++ni) {
                    int nr = wn * 40 + ni * 8 + (l & 7);
                    ldsm_x2(bf[ni], smem_u32(Bp + nr * BSTRIDE + ao + k0 + ((l >> 3) << 3)));
                }
                #pragma unroll
                for (int mi = 0; mi < 4; ++mi)
                    #pragma unroll
                    for (int ni = 0; ni < 5; ++ni)
                        mma_bf16(acc[mi][ni], af[mi], bf[ni]);
            }
        }
    };

    // prime pipeline
    int tile = blockIdx.x;
    issue_x(XS0_OFF, imu_h, tile);
    issue_x(XS1_OFF, vid_h, tile);

    for (; tile < NTILES; tile += GRID) {
        const int nxt = tile + GRID;
        const bool hasNext = nxt < NTILES;

        issue_b(0);                        // pending: imu(i), vid(i), B0
        CPWAIT(2); __syncthreads();        // imu(i) done
        convert_x(XS0_OFF);
        CPWAIT(0); __syncthreads();        // vid(i), B0 done

        #pragma unroll
        for (int a = 0; a < 4; ++a)
            #pragma unroll
            for (int b_ = 0; b_ < 5; ++b_)
                #pragma unroll
                for (int c = 0; c < 4; ++c) { acc0[a][b_][c] = 0.f; acc1[a][b_][c] = 0.f; }

        mma_all(XS0_OFF, acc0);
        __syncthreads();

        issue_b(1);                        // commit B1 first
        if (hasNext) issue_x(XS0_OFF, imu_h, nxt);
        convert_x(XS1_OFF);
        if (hasNext) { CPWAIT(1); } else { CPWAIT(0); }   // B1 done
        __syncthreads();

        mma_all(XS1_OFF, acc1);
        __syncthreads();

        if (hasNext) issue_x(XS1_OFF, vid_h, nxt);

        // ---- epilogue: G overlays Bs ----
        float* G = (float*)(smem + BS_OFF);
        float* seqs = (float*)(smem + BS_OFF + 83968);
        #pragma unroll
        for (int ni = 0; ni < 5; ++ni) {
            int col0 = wn * 40 + ni * 8 + 2 * (lane & 3);
            float a00 = ALB[col0], a01 = ALB[col0 + 1];
            float a10 = ALB[160 + col0], a11 = ALB[160 + col0 + 1];
            #pragma unroll
            for (int mi = 0; mi < 4; ++mi) {
                int r0 = wm * 64 + mi * 16 + (lane >> 2);
                G[r0 * GSTR + col0]           = (acc0[mi][ni][0] + a00) * (acc1[mi][ni][0] + a10);
                G[r0 * GSTR + col0 + 1]       = (acc0[mi][ni][1] + a01) * (acc1[mi][ni][1] + a11);
                G[(r0 + 8) * GSTR + col0]     = (acc0[mi][ni][2] + a00) * (acc1[mi][ni][2] + a10);
                G[(r0 + 8) * GSTR + col0 + 1] = (acc0[mi][ni][3] + a01) * (acc1[mi][ni][3] + a11);
            }
        }
        __syncthreads();
        for (int i = tid; i < TM * DF; i += NTHREADS) {
            int t = i / DF, d = i - t * DF;
            float s = FB[d];
            #pragma unroll
            for (int r = 0; r < RANK; ++r) s += G[t * GSTR + r * DF + d];
            seqs[i] = s;
        }
        __syncthreads();
        {
            const int j0 = lane * 4;
            float w1r[4][10], b1r[4], w2r[4][2];
            #pragma unroll
            for (int jj = 0; jj < 4; ++jj) {
                b1r[jj] = B1S[j0 + jj];
                w2r[jj][0] = W2[(j0 + jj) * 2];
                w2r[jj][1] = W2[(j0 + jj) * 2 + 1];
                #pragma unroll
                for (int d = 0; d < 10; ++d) w1r[jj][d] = W1S[d * 128 + j0 + jj];
            }
            const int bi = tile >> 5;
            const float inv = 1.0f / (anthro[bi * 2] * anthro[bi * 2 + 1]);
            const float b2a = b2[0], b2b = b2[1];
            for (int tt = 0; tt < 16; ++tt) {
                int t = warp * 16 + tt;
                float sd[10];
                #pragma unroll
                for (int d = 0; d < 10; ++d) sd[d] = seqs[t * DF + d];
                float o0 = 0.f, o1 = 0.f;
                #pragma unroll
                for (int jj = 0; jj < 4; ++jj) {
                    float h = b1r[jj];
                    #pragma unroll
                    for (int d = 0; d < 10; ++d) h += sd[d] * w1r[jj][d];
                    h = fmaxf(h, 0.f);
                    o0 += h * w2r[jj][0];
                    o1 += h * w2r[jj][1];
                }
                #pragma unroll
                for (int off = 16; off; off >>= 1) {
                    o0 += __shfl_xor_sync(0xffffffffu, o0, off);
                    o1 += __shfl_xor_sync(0xffffffffu, o1, off);
                }
                if (lane == 0) {
                    long tok = (long)tile * TM + t;
                    ((float2*)out)[tok] = make_float2((o0 + b2a) * inv, (o1 + b2b) * inv);
                }
            }
        }
        __syncthreads();   // G dead before next tile's B0 lands
    }
}

// ---------- launch ----------
extern "C" void kernel_launch(void* const* d_in, const int* in_sizes, int n_in,
                              void* d_out, int out_size)
{
    (void)in_sizes; (void)n_in; (void)out_size;
    const float* imu_h      = (const float*)d_in[0];
    const float* vid_h      = (const float*)d_in[1];
    const float* anthro     = (const float*)d_in[2];
    const float* imu_factor = (const float*)d_in[3];
    const float* vid_factor = (const float*)d_in[4];
    const float* fusion_w   = (const float*)d_in[5];
    const float* fusion_b   = (const float*)d_in[6];
    const float* W1         = (const float*)d_in[7];
    const float* b1         = (const float*)d_in[8];
    const float* W2         = (const float*)d_in[9];
    const float* b2         = (const float*)d_in[10];
    float* out = (float*)d_out;

    cudaFuncSetAttribute(fusion_main, cudaFuncAttributeMaxDynamicSharedMemorySize, SMEM_BYTES);

    const int prep_total = 2 * NCOL * BSTRIDE + 2 * NCOL;
    prep_kernel<<<(prep_total + 255) / 256, 256>>>(imu_factor, vid_factor, fusion_w);
    fusion_main<<<GRID, NTHREADS, SMEM_BYTES>>>(
        imu_h, vid_h, anthro, fusion_b, W1, b1, W2, b2, out);
}